// round 8
// baseline (speedup 1.0000x reference)
#include <cuda_runtime.h>
#include <cstdint>
#include <cstddef>

// Problem dims (fixed by the dataset)
#define B_ 64
#define S_ 1024
#define I_ 512
#define H_ 1024
#define O_ 512

typedef unsigned long long ull;

// ---------------- scratch (no cudaMalloc allowed) ----------------
__device__ float g_xp[(size_t)B_ * S_ * H_];  // x-projection (B*S, H)
__device__ float g_hs[(size_t)B_ * S_ * H_];  // hidden states [b][s][H]
__device__ unsigned g_bar4[4 * 32];           // 4 padded barrier counters

// ---------------- helpers ----------------
__device__ __forceinline__ ull fma2(ull a, ull b, ull c) {
    ull d;
    asm("fma.rn.f32x2 %0, %1, %2, %3;" : "=l"(d) : "l"(a), "l"(b), "l"(c));
    return d;
}
__device__ __forceinline__ ull add2(ull a, ull b) {
    ull d;
    asm("add.rn.f32x2 %0, %1, %2;" : "=l"(d) : "l"(a), "l"(b));
    return d;
}
__device__ __forceinline__ ull pack2(float x, float y) {
    ull d; asm("mov.b64 %0, {%1, %2};" : "=l"(d) : "f"(x), "f"(y)); return d;
}
__device__ __forceinline__ void unpack2(ull v, float& lo, float& hi) {
    asm("mov.b64 {%0, %1}, %2;" : "=f"(lo), "=f"(hi) : "l"(v));
}
__device__ __forceinline__ uint32_t smem_u32(const void* p) {
    uint32_t a;
    asm("{ .reg .u64 t; cvta.to.shared.u64 t, %1; cvt.u32.u64 %0, t; }"
        : "=r"(a) : "l"(p));
    return a;
}
__device__ __forceinline__ void cp16(uint32_t saddr, const void* g) {
    asm volatile("cp.async.cg.shared.global [%0], [%1], 16;" :: "r"(saddr), "l"(g));
}
#define CP_COMMIT() asm volatile("cp.async.commit_group;" ::: "memory")
#define CP_WAIT(n)  asm volatile("cp.async.wait_group %0;" :: "n"(n) : "memory")

// Accurate tanh, robust under --use_fast_math.
__device__ __forceinline__ float tanh_acc(float x) {
    float ax = fabsf(x);
    float e  = __expf(-2.0f * ax);
    float r  = (1.0f - e) / (1.0f + e);
    return copysignf(r, x);
}

__global__ void zero_bar() {
    if (threadIdx.x < 4 * 32) g_bar4[threadIdx.x] = 0u;
}

// ---------------- NT GEMM with f32x2 FMA ----------------
__global__ void __launch_bounds__(256)
gemm_nt_bias(const float* __restrict__ A, const float* __restrict__ Bm,
             const float* __restrict__ bias0, const float* __restrict__ bias1,
             float* __restrict__ C, int M, int N, int K)
{
    const int BK = 16;
    __shared__ float As[16][128 + 4];
    __shared__ float Bs[16][128 + 4];

    int t  = threadIdx.x;
    int tx = t & 15;
    int ty = t >> 4;
    int bm = blockIdx.y * 128;
    int bn = blockIdx.x * 128;

    ull acc2[8][4];
#pragma unroll
    for (int i = 0; i < 8; i++)
#pragma unroll
        for (int j = 0; j < 4; j++) acc2[i][j] = 0ull;

    for (int kc = 0; kc < K; kc += BK) {
#pragma unroll
        for (int i = 0; i < 2; i++) {
            int id = t + i * 256;
            int r  = id >> 2;
            int c4 = id & 3;
            float4 va = *(const float4*)(A  + (size_t)(bm + r) * K + kc + c4 * 4);
            As[c4 * 4 + 0][r] = va.x; As[c4 * 4 + 1][r] = va.y;
            As[c4 * 4 + 2][r] = va.z; As[c4 * 4 + 3][r] = va.w;
            float4 vb = *(const float4*)(Bm + (size_t)(bn + r) * K + kc + c4 * 4);
            Bs[c4 * 4 + 0][r] = vb.x; Bs[c4 * 4 + 1][r] = vb.y;
            Bs[c4 * 4 + 2][r] = vb.z; Bs[c4 * 4 + 3][r] = vb.w;
        }
        __syncthreads();
#pragma unroll
        for (int k = 0; k < BK; k++) {
            float4 a0 = *(const float4*)&As[k][ty * 8];
            float4 a1 = *(const float4*)&As[k][ty * 8 + 4];
            ulonglong2 b0 = *(const ulonglong2*)&Bs[k][tx * 8];
            ulonglong2 b1 = *(const ulonglong2*)&Bs[k][tx * 8 + 4];
            ull bb[4] = { b0.x, b0.y, b1.x, b1.y };
            ull a2[8];
            a2[0] = pack2(a0.x, a0.x); a2[1] = pack2(a0.y, a0.y);
            a2[2] = pack2(a0.z, a0.z); a2[3] = pack2(a0.w, a0.w);
            a2[4] = pack2(a1.x, a1.x); a2[5] = pack2(a1.y, a1.y);
            a2[6] = pack2(a1.z, a1.z); a2[7] = pack2(a1.w, a1.w);
#pragma unroll
            for (int i = 0; i < 8; i++)
#pragma unroll
                for (int j = 0; j < 4; j++)
                    acc2[i][j] = fma2(a2[i], bb[j], acc2[i][j]);
        }
        __syncthreads();
    }

    float bs[8];
#pragma unroll
    for (int j = 0; j < 8; j++) {
        int n = bn + tx * 8 + j;
        bs[j] = bias0[n] + (bias1 ? bias1[n] : 0.0f);
    }
#pragma unroll
    for (int i = 0; i < 8; i++) {
        float acc[8];
#pragma unroll
        for (int j = 0; j < 4; j++)
            unpack2(acc2[i][j], acc[2 * j], acc[2 * j + 1]);
        size_t row = (size_t)(bm + ty * 8 + i) * N + bn + tx * 8;
        float4 v0 = make_float4(acc[0] + bs[0], acc[1] + bs[1],
                                acc[2] + bs[2], acc[3] + bs[3]);
        float4 v1 = make_float4(acc[4] + bs[4], acc[5] + bs[5],
                                acc[6] + bs[6], acc[7] + bs[7]);
        *(float4*)(C + row)     = v0;
        *(float4*)(C + row + 4) = v1;
    }
}

// ---------------- persistent recurrence, W_hh in registers ----------------
// 128 blocks x 512 threads (1/SM, 4 warps/SMSP for latency hiding).
// Block bx: cols n0=(bx>>2)*32, batches m0=(bx&3)*16. Warp w owns k-chunk
// [64w, 64w+64); lane l owns column n0+l (32 packed f32x2 W registers,
// persistent across all steps). Per step each warp cp.asyncs its own 4KB
// h-slice, computes 16 dot-chunks with distance-1 software-pipelined LDS,
// writes k-partials; syncthreads; 512 threads reduce 16 partials + tanh +
// store; 32-way batch-group barrier (release/acquire).
#define RBLK 128
#define RTHR 512
#define NW   16
#define KCH  64                                   // k per warp
#define PARTP 33
#define HSM_F (NW * 16 * KCH)                     // 16384 floats = 64KB
#define REC_SMEM ((HSM_F + NW * 16 * PARTP) * 4)

__global__ void __launch_bounds__(RTHR, 1)
rnn_recurrence(const float* __restrict__ xp, const float* __restrict__ Whh,
               const float* __restrict__ h0, float* __restrict__ hs)
{
    extern __shared__ float sm[];
    float* hsm  = sm;                 // [warp][batch][64]
    float* part = sm + HSM_F;         // [16][16][PARTP]

    const int t   = threadIdx.x;
    const int bx  = blockIdx.x;
    const int n0  = (bx >> 2) * 32;   // first col of this block
    const int grp = bx & 3;           // batch group
    const int m0  = grp * 16;         // first batch
    const int w   = t >> 5;           // warp: k-chunk owner
    const int l   = t & 31;           // lane: column owner
    const int k0  = w * KCH;

    // epilogue mapping: one output per thread
    const int eb = t >> 5;            // batch 0..15
    const int ec = t & 31;            // col 0..31

    // Load this lane's W_hh column-slice into registers (once).
    ull Wreg[32];
    {
        const float2* wrow = (const float2*)(Whh + (size_t)(n0 + l) * H_ + k0);
#pragma unroll
        for (int j = 0; j < 32; j++) {
            float2 v = wrow[j];
            Wreg[j] = pack2(v.x, v.y);
        }
    }

    // warp-private staging base (bytes): hsm[w][r][.]
    const uint32_t hw_u32 = smem_u32(hsm) + (uint32_t)(w * 16 * KCH) * 4;
    volatile unsigned* bar = (volatile unsigned*)&g_bar4[grp * 32];

    unsigned target = 0;
    for (int s = 0; s < S_; s++) {
        const float* hsrc;
        size_t rstride;
        if (s == 0) { hsrc = h0 + (size_t)m0 * H_;                  rstride = H_; }
        else        { hsrc = hs + ((size_t)m0 * S_ + (s - 1)) * H_; rstride = (size_t)S_ * H_; }

        // warp-local stage: 16 rows x 256B of this warp's k-chunk (8 cp16/lane)
        const float* srcb = hsrc + k0;
#pragma unroll
        for (int i = 0; i < 8; i++) {
            int id = i * 32 + l;       // 0..255
            int r  = id >> 4;          // row 0..15
            int c  = id & 15;          // float4 col 0..15
            cp16(hw_u32 + (uint32_t)(r * KCH + c * 4) * 4,
                 srcb + (size_t)r * rstride + c * 4);
        }
        CP_COMMIT();

        // prefetch xp for this step's epilogue (hidden under compute)
        size_t oidx = ((size_t)(m0 + eb) * S_ + s) * H_ + n0 + ec;
        float xv = xp[oidx];

        CP_WAIT(0);
        __syncwarp();

        // 16 dot-chunks: h broadcast from smem (pipelined), W in registers
        {
            const ulonglong2* hb = (const ulonglong2*)(hsm + w * 16 * KCH);
            ulonglong2 c0 = hb[0], c1 = hb[1], c2 = hb[2], c3 = hb[3];
#pragma unroll 4
            for (int b = 0; b < 16; b++) {
                ull a0 = 0, a1 = 0, a2 = 0, a3 = 0;
#pragma unroll
                for (int u = 0; u < 16; u += 4) {
                    // prefetch next 4 ulonglong2 (crosses into next b at u=12;
                    // final overrun lands in the partials region, unused)
                    ulonglong2 p0 = hb[u + 4], p1 = hb[u + 5];
                    ulonglong2 p2 = hb[u + 6], p3 = hb[u + 7];
                    a0 = fma2(c0.x, Wreg[2 * u + 0], a0);
                    a1 = fma2(c0.y, Wreg[2 * u + 1], a1);
                    a2 = fma2(c1.x, Wreg[2 * u + 2], a2);
                    a3 = fma2(c1.y, Wreg[2 * u + 3], a3);
                    a0 = fma2(c2.x, Wreg[2 * u + 4], a0);
                    a1 = fma2(c2.y, Wreg[2 * u + 5], a1);
                    a2 = fma2(c3.x, Wreg[2 * u + 6], a2);
                    a3 = fma2(c3.y, Wreg[2 * u + 7], a3);
                    c0 = p0; c1 = p1; c2 = p2; c3 = p3;
                }
                float x0, x1;
                unpack2(add2(add2(a0, a1), add2(a2, a3)), x0, x1);
                part[(w * 16 + b) * PARTP + l] = x0 + x1;
                hb += 16;
            }
        }
        __syncthreads();

        // reduce 16 k-partials, add xp, tanh, store (1 output/thread)
        {
            float s0 = 0.f;
#pragma unroll
            for (int w16 = 0; w16 < NW; w16++)
                s0 += part[(w16 * 16 + eb) * PARTP + ec];
            hs[oidx] = tanh_acc(s0 + xv);
        }

        // 32-way batch-group barrier (release add + acquire spin)
        target += 32;
        __syncthreads();
        if (t == 0) {
            asm volatile("red.release.gpu.global.add.u32 [%0], %1;"
                         :: "l"(bar), "r"(1u) : "memory");
            unsigned v;
            do {
                asm volatile("ld.acquire.gpu.global.u32 %0, [%1];"
                             : "=r"(v) : "l"(bar) : "memory");
            } while (v < target);
        }
        __syncthreads();
    }
}

// last_hidden[b][k] = hs[b][S-1][k]
__global__ void copy_last(const float* __restrict__ hs, float* __restrict__ out)
{
    int i = blockIdx.x * 256 + threadIdx.x;
    int b = i >> 10, k = i & (H_ - 1);
    out[i] = hs[((size_t)b * S_ + (S_ - 1)) * H_ + k];
}

// ---------------- launch ----------------
extern "C" void kernel_launch(void* const* d_in, const int* in_sizes, int n_in,
                              void* d_out, int out_size)
{
    const float* inputs = (const float*)d_in[0];
    const float* h0     = (const float*)d_in[1];
    const float* W_ih   = (const float*)d_in[2];
    const float* b_ih   = (const float*)d_in[3];
    const float* W_hh   = (const float*)d_in[4];
    const float* b_hh   = (const float*)d_in[5];
    const float* W_ho   = (const float*)d_in[6];
    const float* b_ho   = (const float*)d_in[7];
    float* out = (float*)d_out;

    float *xp, *hs;
    cudaGetSymbolAddress((void**)&xp, g_xp);
    cudaGetSymbolAddress((void**)&hs, g_hs);

    cudaFuncSetAttribute(rnn_recurrence,
                         cudaFuncAttributeMaxDynamicSharedMemorySize, REC_SMEM);

    zero_bar<<<1, 128>>>();

    // xp = inputs @ W_ih^T + b_ih + b_hh   (M=B*S, N=H, K=I)
    dim3 g1(H_ / 128, (B_ * S_) / 128);
    gemm_nt_bias<<<g1, 256>>>(inputs, W_ih, b_ih, b_hh, xp, B_ * S_, H_, I_);

    // sequential scan, persistent kernel
    rnn_recurrence<<<RBLK, RTHR, REC_SMEM>>>(xp, W_hh, h0, hs);

    // outputs = hs @ W_ho^T + b_ho         (M=B*S, N=O, K=H)
    dim3 g2(O_ / 128, (B_ * S_) / 128);
    gemm_nt_bias<<<g2, 256>>>(hs, W_ho, b_ho, nullptr, out, B_ * S_, O_, H_);

    // last_hidden appended after outputs
    copy_last<<<(B_ * H_) / 256, 256>>>(hs, out + (size_t)B_ * S_ * O_);
}